// round 8
// baseline (speedup 1.0000x reference)
#include <cuda_runtime.h>
#include <math.h>

// Shapes are fixed by the problem: b=4, h=w=64, c=512, HEADS=8, DIM_HEAD=64.
#define M_TOTAL 16384          // b * h * w
#define C_DIM   512
#define NPIX    16384

typedef unsigned long long ull;

// Scratch (no cudaMalloc allowed) — static device globals.
__device__ float g_q[M_TOTAL * C_DIM];
__device__ float g_k[M_TOTAL * C_DIM];
__device__ float g_v[M_TOTAL * C_DIM];   // holds 2 * (x @ Wv^T)
__device__ float g_mid[M_TOTAL * C_DIM]; // scrambled attention output (pre-projection)

// ---- packed fp32x2 helpers (Blackwell FFMA2) ----
__device__ __forceinline__ ull dup2(float x) {
    ull r; asm("mov.b64 %0, {%1, %1};" : "=l"(r) : "f"(x)); return r;
}
__device__ __forceinline__ void fma2(ull& d, ull a, ull b) {
    asm("fma.rn.f32x2 %0, %1, %2, %0;" : "+l"(d) : "l"(a), "l"(b));
}
__device__ __forceinline__ float2 unpack2(ull v) {
    float2 f; asm("mov.b64 {%0, %1}, %2;" : "=f"(f.x), "=f"(f.y) : "l"(v)); return f;
}

// ============================================================================
// Kernel 1: fused QKV GEMM.  q = X@Wq^T, k = X@Wk^T, v = 2*(X@Wv^T)
// X:[16384,512]  W*:[512,512] row-major (output feature = row, K contiguous)
// 64x64 tile per block, 256 threads, 4x4 micro-tile per thread, 3 outputs
// sharing the A tile. Packed f32x2 accumulators (2 N-columns per reg pair).
// ============================================================================
__global__ __launch_bounds__(256) void qkv_gemm_kernel(
    const float* __restrict__ X,  const float* __restrict__ Wq,
    const float* __restrict__ Wk, const float* __restrict__ Wv)
{
    __shared__ float As [16][68];
    __shared__ float Bqs[16][68];
    __shared__ float Bks[16][68];
    __shared__ float Bvs[16][68];

    const int tid = threadIdx.x;
    const int m0 = (blockIdx.x >> 3) << 6;   // 256 m-tiles
    const int n0 = (blockIdx.x & 7)  << 6;   // 8 n-tiles
    const int lr = tid >> 2;                 // 0..63 : tile row loaded
    const int lk = (tid & 3) << 2;           // 0,4,8,12 : k-chunk loaded
    const int ty = tid >> 4;                 // 0..15
    const int tx = tid & 15;                 // 0..15

    const float* pA = X  + (size_t)(m0 + lr) * C_DIM + lk;
    const float* pQ = Wq + (size_t)(n0 + lr) * C_DIM + lk;
    const float* pK = Wk + (size_t)(n0 + lr) * C_DIM + lk;
    const float* pV = Wv + (size_t)(n0 + lr) * C_DIM + lk;

    ull cq[4][2] = {}, ck[4][2] = {}, cv[4][2] = {};

    for (int k0 = 0; k0 < C_DIM; k0 += 16) {
        float4 a4 = *(const float4*)(pA + k0);
        float4 q4 = *(const float4*)(pQ + k0);
        float4 k4 = *(const float4*)(pK + k0);
        float4 v4 = *(const float4*)(pV + k0);
        __syncthreads();   // previous compute done reading smem
        As [lk+0][lr]=a4.x; As [lk+1][lr]=a4.y; As [lk+2][lr]=a4.z; As [lk+3][lr]=a4.w;
        Bqs[lk+0][lr]=q4.x; Bqs[lk+1][lr]=q4.y; Bqs[lk+2][lr]=q4.z; Bqs[lk+3][lr]=q4.w;
        Bks[lk+0][lr]=k4.x; Bks[lk+1][lr]=k4.y; Bks[lk+2][lr]=k4.z; Bks[lk+3][lr]=k4.w;
        Bvs[lk+0][lr]=v4.x; Bvs[lk+1][lr]=v4.y; Bvs[lk+2][lr]=v4.z; Bvs[lk+3][lr]=v4.w;
        __syncthreads();
        #pragma unroll
        for (int kk = 0; kk < 16; kk++) {
            float4 av = *(const float4*)&As[kk][ty << 2];
            ull a0 = dup2(av.x), a1 = dup2(av.y), a2 = dup2(av.z), a3 = dup2(av.w);
            ulonglong2 bq = *(const ulonglong2*)&Bqs[kk][tx << 2];
            ulonglong2 bk = *(const ulonglong2*)&Bks[kk][tx << 2];
            ulonglong2 bv = *(const ulonglong2*)&Bvs[kk][tx << 2];
            fma2(cq[0][0],a0,bq.x); fma2(cq[0][1],a0,bq.y);
            fma2(cq[1][0],a1,bq.x); fma2(cq[1][1],a1,bq.y);
            fma2(cq[2][0],a2,bq.x); fma2(cq[2][1],a2,bq.y);
            fma2(cq[3][0],a3,bq.x); fma2(cq[3][1],a3,bq.y);
            fma2(ck[0][0],a0,bk.x); fma2(ck[0][1],a0,bk.y);
            fma2(ck[1][0],a1,bk.x); fma2(ck[1][1],a1,bk.y);
            fma2(ck[2][0],a2,bk.x); fma2(ck[2][1],a2,bk.y);
            fma2(ck[3][0],a3,bk.x); fma2(ck[3][1],a3,bk.y);
            fma2(cv[0][0],a0,bv.x); fma2(cv[0][1],a0,bv.y);
            fma2(cv[1][0],a1,bv.x); fma2(cv[1][1],a1,bv.y);
            fma2(cv[2][0],a2,bv.x); fma2(cv[2][1],a2,bv.y);
            fma2(cv[3][0],a3,bv.x); fma2(cv[3][1],a3,bv.y);
        }
    }

    #pragma unroll
    for (int i = 0; i < 4; i++) {
        size_t off = (size_t)(m0 + (ty << 2) + i) * C_DIM + n0 + (tx << 2);
        float2 q0 = unpack2(cq[i][0]), q1 = unpack2(cq[i][1]);
        *(float4*)(g_q + off) = make_float4(q0.x, q0.y, q1.x, q1.y);
        float2 k0f = unpack2(ck[i][0]), k1f = unpack2(ck[i][1]);
        *(float4*)(g_k + off) = make_float4(k0f.x, k0f.y, k1f.x, k1f.y);
        float2 v0 = unpack2(cv[i][0]), v1 = unpack2(cv[i][1]);
        *(float4*)(g_v + off) = make_float4(2.f*v0.x, 2.f*v0.y, 2.f*v1.x, 2.f*v1.y);
    }
}

// ============================================================================
// Kernel 2: per-pixel two-stage attention. One pixel per 64-thread block.
// Writes the (0,3,1,2)-transpose scramble directly:
//   mid[b, e*64 + a, 8r + h] = out[b, nn=64a+r, h, e]
// ============================================================================
__global__ __launch_bounds__(64) void attn_kernel()
{
    __shared__ float qsp[8][68], ksp[8][68], vsp[8][68];   // padded: stride-68 kills head-stride conflicts
    __shared__ float nfq[8], nfk[8], nfv[8];
    __shared__ float A1raw[8][8];
    __shared__ float A1q[8][8], A1k[8][8];                 // softmax(A1) * norm-factor folded in
    __shared__ float q2s[8][68], k2s[8][68];
    __shared__ float attnS[64][65];

    const int t = threadIdx.x;          // 0..63
    const int p = blockIdx.x;           // pixel
    const float* gq = g_q + (size_t)p * C_DIM;
    const float* gk = g_k + (size_t)p * C_DIM;
    const float* gv = g_v + (size_t)p * C_DIM;

    #pragma unroll
    for (int i = 0; i < 8; i++) {
        qsp[i][t] = gq[i*64 + t];
        ksp[i][t] = gk[i*64 + t];
        vsp[i][t] = gv[i*64 + t];
    }
    __syncthreads();

    // --- l2 norm factors for q, k, v (24 tasks) ---
    if (t < 24) {
        int m = t >> 3, h = t & 7;
        const float* src = (m == 0) ? &qsp[h][0] : (m == 1) ? &ksp[h][0] : &vsp[h][0];
        float ss = 0.f;
        #pragma unroll
        for (int d = 0; d < 64; d += 4) {
            float4 x4 = *(const float4*)&src[d];
            ss += x4.x*x4.x + x4.y*x4.y + x4.z*x4.z + x4.w*x4.w;
        }
        float nf = 1.0f / fmaxf(sqrtf(ss), 1e-12f);
        if (m == 0) nfq[h] = nf; else if (m == 1) nfk[h] = nf; else nfv[h] = nf;
    }
    __syncthreads();

    // --- stage-1 logits: A1[h,g] = <vn_h, vn_g> ---
    {
        int h = t >> 3, g = t & 7;
        float dot = 0.f;
        #pragma unroll
        for (int d = 0; d < 64; d += 4) {
            float4 a = *(const float4*)&vsp[h][d];
            float4 b = *(const float4*)&vsp[g][d];
            dot += a.x*b.x + a.y*b.y + a.z*b.z + a.w*b.w;
        }
        A1raw[h][g] = dot * nfv[h] * nfv[g];
    }
    __syncthreads();

    // --- stage-1 softmax over g; fold q/k norm factors in ---
    if (t < 8) {
        float r[8]; float mx = -1e30f;
        #pragma unroll
        for (int g = 0; g < 8; g++) { r[g] = A1raw[t][g]; mx = fmaxf(mx, r[g]); }
        float s = 0.f;
        #pragma unroll
        for (int g = 0; g < 8; g++) { r[g] = __expf(r[g] - mx); s += r[g]; }
        float inv = 1.0f / s;
        #pragma unroll
        for (int g = 0; g < 8; g++) {
            float pg = r[g] * inv;
            A1q[t][g] = pg * nfq[g];
            A1k[t][g] = pg * nfk[g];
        }
    }
    __syncthreads();

    // --- head mix: q2[h,d] = sum_g A1q[h,g]*q[g,d] ; k2 likewise. d = t ---
    {
        float aq[8] = {}, ak[8] = {};
        #pragma unroll
        for (int g = 0; g < 8; g++) {
            float qv = qsp[g][t], kv = ksp[g][t];
            #pragma unroll
            for (int h = 0; h < 8; h++) {
                aq[h] += A1q[h][g] * qv;
                ak[h] += A1k[h][g] * kv;
            }
        }
        #pragma unroll
        for (int h = 0; h < 8; h++) { q2s[h][t] = aq[h]; k2s[h][t] = ak[h]; }
    }
    __syncthreads();

    // --- stage-2: attn[d,e] = sum_h k2[h,d]*q2[h,e], softmax over e. d = t ---
    {
        float row[64];
        #pragma unroll
        for (int e = 0; e < 64; e++) row[e] = 0.f;
        #pragma unroll
        for (int h = 0; h < 8; h++) {
            float kh = k2s[h][t];
            #pragma unroll
            for (int e = 0; e < 64; e += 4) {
                float4 q4 = *(const float4*)&q2s[h][e];
                row[e+0] += kh * q4.x;
                row[e+1] += kh * q4.y;
                row[e+2] += kh * q4.z;
                row[e+3] += kh * q4.w;
            }
        }
        float mx = row[0];
        #pragma unroll
        for (int e = 1; e < 64; e++) mx = fmaxf(mx, row[e]);
        float s = 0.f;
        #pragma unroll
        for (int e = 0; e < 64; e++) { row[e] = __expf(row[e] - mx); s += row[e]; }
        float inv = 1.0f / s;
        #pragma unroll
        for (int e = 0; e < 64; e++) attnS[t][e] = row[e] * inv;
    }
    __syncthreads();

    // --- out[h,e] = sum_d v[h,d]*attn[d,e].  e = t (column owner) ---
    float o[8] = {};
    #pragma unroll
    for (int d = 0; d < 64; d += 4) {
        float a0 = attnS[d+0][t], a1 = attnS[d+1][t];
        float a2 = attnS[d+2][t], a3 = attnS[d+3][t];
        #pragma unroll
        for (int h = 0; h < 8; h++) {
            float4 v4 = *(const float4*)&vsp[h][d];
            o[h] += v4.x*a0 + v4.y*a1 + v4.z*a2 + v4.w*a3;
        }
    }

    // scramble: mid[b, t*64 + a, 8r + h],  nn = 64a + r
    int bIdx = p >> 12;
    int nn   = p & 4095;
    int a    = nn >> 6, r = nn & 63;
    float* dst = g_mid + (size_t)bIdx * 4096 * C_DIM
                       + ((size_t)t * 64 + a) * C_DIM + (r << 3);
    ((float4*)dst)[0] = make_float4(o[0], o[1], o[2], o[3]);
    ((float4*)dst)[1] = make_float4(o[4], o[5], o[6], o[7]);
}

// ============================================================================
// Kernel 3: projection.  out = mid @ proj_w^T + proj_b
// 64x128 tile, 256 threads, 4x8 micro-tile, packed f32x2.
// ============================================================================
__global__ __launch_bounds__(256) void proj_gemm_kernel(
    const float* __restrict__ W, const float* __restrict__ bias,
    float* __restrict__ out)
{
    __shared__ float As[16][68];
    __shared__ float Bs[16][132];

    const int tid = threadIdx.x;
    const int m0 = (blockIdx.x >> 2) << 6;   // 256 m-tiles
    const int n0 = (blockIdx.x & 3)  << 7;   // 4 n-tiles of 128
    const int lr = tid >> 2;
    const int lk = (tid & 3) << 2;
    const int ty = tid >> 4;
    const int tx = tid & 15;

    const float* pA  = g_mid + (size_t)(m0 + lr)      * C_DIM + lk;
    const float* pB0 = W     + (size_t)(n0 + lr)      * C_DIM + lk;
    const float* pB1 = W     + (size_t)(n0 + 64 + lr) * C_DIM + lk;

    ull c[4][4] = {};

    for (int k0 = 0; k0 < C_DIM; k0 += 16) {
        float4 a4 = *(const float4*)(pA  + k0);
        float4 b4 = *(const float4*)(pB0 + k0);
        float4 b5 = *(const float4*)(pB1 + k0);
        __syncthreads();
        As[lk+0][lr]=a4.x; As[lk+1][lr]=a4.y; As[lk+2][lr]=a4.z; As[lk+3][lr]=a4.w;
        Bs[lk+0][lr]=b4.x; Bs[lk+1][lr]=b4.y; Bs[lk+2][lr]=b4.z; Bs[lk+3][lr]=b4.w;
        Bs[lk+0][64+lr]=b5.x; Bs[lk+1][64+lr]=b5.y; Bs[lk+2][64+lr]=b5.z; Bs[lk+3][64+lr]=b5.w;
        __syncthreads();
        #pragma unroll
        for (int kk = 0; kk < 16; kk++) {
            float4 av = *(const float4*)&As[kk][ty << 2];
            ull a0 = dup2(av.x), a1 = dup2(av.y), a2 = dup2(av.z), a3 = dup2(av.w);
            ulonglong2 b0 = *(const ulonglong2*)&Bs[kk][(tx << 3) + 0];
            ulonglong2 b1 = *(const ulonglong2*)&Bs[kk][(tx << 3) + 4];
            fma2(c[0][0],a0,b0.x); fma2(c[0][1],a0,b0.y); fma2(c[0][2],a0,b1.x); fma2(c[0][3],a0,b1.y);
            fma2(c[1][0],a1,b0.x); fma2(c[1][1],a1,b0.y); fma2(c[1][2],a1,b1.x); fma2(c[1][3],a1,b1.y);
            fma2(c[2][0],a2,b0.x); fma2(c[2][1],a2,b0.y); fma2(c[2][2],a2,b1.x); fma2(c[2][3],a2,b1.y);
            fma2(c[3][0],a3,b0.x); fma2(c[3][1],a3,b0.y); fma2(c[3][2],a3,b1.x); fma2(c[3][3],a3,b1.y);
        }
    }

    float4 bb0 = *(const float4*)(bias + n0 + (tx << 3));
    float4 bb1 = *(const float4*)(bias + n0 + (tx << 3) + 4);
    #pragma unroll
    for (int i = 0; i < 4; i++) {
        size_t off = (size_t)(m0 + (ty << 2) + i) * C_DIM + n0 + (tx << 3);
        float2 c0 = unpack2(c[i][0]), c1 = unpack2(c[i][1]);
        float2 c2 = unpack2(c[i][2]), c3 = unpack2(c[i][3]);
        *(float4*)(out + off)     = make_float4(c0.x+bb0.x, c0.y+bb0.y, c1.x+bb0.z, c1.y+bb0.w);
        *(float4*)(out + off + 4) = make_float4(c2.x+bb1.x, c2.y+bb1.y, c3.x+bb1.z, c3.y+bb1.w);
    }
}

// ============================================================================
extern "C" void kernel_launch(void* const* d_in, const int* in_sizes, int n_in,
                              void* d_out, int out_size)
{
    const float* x  = (const float*)d_in[0];
    const float* Wq = (const float*)d_in[1];
    const float* Wk = (const float*)d_in[2];
    const float* Wv = (const float*)d_in[3];
    // d_in[4] = conv_w : mathematically dead in the reference (v += v overwrite)
    const float* Pw = (const float*)d_in[5];
    const float* Pb = (const float*)d_in[6];
    float* out = (float*)d_out;

    qkv_gemm_kernel<<<2048, 256>>>(x, Wq, Wk, Wv);
    attn_kernel<<<NPIX, 64>>>();
    proj_gemm_kernel<<<1024, 256>>>(Pw, Pb, out);
}

// round 13
// speedup vs baseline: 1.9037x; 1.9037x over previous
#include <cuda_runtime.h>
#include <math.h>

// Shapes fixed: b=4, h=w=64, c=512, HEADS=8, DIM_HEAD=64.
#define M_TOTAL 16384
#define C_DIM   512
#define NPIX    16384

// Scratch (no cudaMalloc allowed).
__device__ float g_q[M_TOTAL * C_DIM];
__device__ float g_k[M_TOTAL * C_DIM];
__device__ float g_v[M_TOTAL * C_DIM];   // 2 * (x @ Wv^T)
__device__ float g_mid[M_TOTAL * C_DIM]; // scrambled attention output

// ---- tf32 helpers ----
__device__ __forceinline__ unsigned f2tf32(float f) {
    unsigned r; asm("cvt.rna.tf32.f32 %0, %1;" : "=r"(r) : "f"(f)); return r;
}
__device__ __forceinline__ void mma_tf32(float c[4],
    unsigned a0, unsigned a1, unsigned a2, unsigned a3,
    unsigned b0, unsigned b1)
{
    asm("mma.sync.aligned.m16n8k8.row.col.f32.tf32.tf32.f32 "
        "{%0,%1,%2,%3},{%4,%5,%6,%7},{%8,%9},{%0,%1,%2,%3};"
        : "+f"(c[0]), "+f"(c[1]), "+f"(c[2]), "+f"(c[3])
        : "r"(a0), "r"(a1), "r"(a2), "r"(a3), "r"(b0), "r"(b1));
}

// ============================================================================
// Generic tf32 tensor-core GEMM:  C[m,n] = scale * sum_k A[m,k]*W[n,k] (+bias)
// M=16384, N=K=512. Block tile 128x128, 256 threads, warp tile 64x32.
// SMEM: pitch-20 rows (16 k-words + 4 pad) with k-interleave
//   k' = (k&3)*4 + (k>>2)   -> one LDS.128 per row serves both k8 substeps.
// Conflict-free: STS.128 fills, LDS.128 fragment reads (pitch-20 bank walk).
// Double-buffered, one __syncthreads per k16 iteration, register prefetch.
// dst: 0->g_q, 1->g_k, 2->g_v, 3-> A=g_mid, C=Cext (projection).
// ============================================================================
#define PITCH 20

__device__ __forceinline__ uint4 ld_cvt4(const float* p) {
    float4 v = *(const float4*)p;
    uint4 u; u.x = f2tf32(v.x); u.y = f2tf32(v.y); u.z = f2tf32(v.z); u.w = f2tf32(v.w);
    return u;
}
__device__ __forceinline__ void sts_perm(unsigned* buf, int row, int c4, uint4 u) {
    unsigned* p = buf + row * PITCH + c4;   // k' = j*4 + c4  (j = k&3)
    p[0] = u.x; p[4] = u.y; p[8] = u.z; p[12] = u.w;
}

__global__ __launch_bounds__(256, 2) void gemm_tf32_kernel(
    const float* __restrict__ A, const float* __restrict__ W,
    const float* __restrict__ bias, float* __restrict__ Cext,
    int dst, float scale)
{
    __shared__ unsigned sA[2][128 * PITCH];
    __shared__ unsigned sB[2][128 * PITCH];

    const float* Ap = (dst == 3) ? g_mid : A;
    float* C = (dst == 0) ? g_q : (dst == 1) ? g_k : (dst == 2) ? g_v : Cext;

    const int tid = threadIdx.x;
    const int bx  = blockIdx.x;
    const int m0  = (bx >> 2) << 7;          // 128 m-tiles
    const int n0  = (bx & 3)  << 7;          // 4 n-tiles

    // tile loaders: rows lrow and lrow+64, one float4 (k-chunk c4) each
    const int lrow = tid >> 2;
    const int lc4  = tid & 3;                // c' = k>>2
    const float* gA = Ap + (size_t)(m0 + lrow) * C_DIM + (lc4 << 2);
    const float* gB = W  + (size_t)(n0 + lrow) * C_DIM + (lc4 << 2);

    // warp coords
    const int w    = tid >> 5;
    const int lane = tid & 31;
    const int gid  = lane >> 2;
    const int tig  = lane & 3;
    const int wm   = (w >> 2) * 64;          // 0 / 64
    const int wn   = (w & 3)  * 32;          // 0 / 32 / 64 / 96

    float acc[4][4][4];
    #pragma unroll
    for (int i = 0; i < 4; i++)
        #pragma unroll
        for (int j = 0; j < 4; j++)
            #pragma unroll
            for (int q = 0; q < 4; q++) acc[i][j][q] = 0.f;

    uint4 ra0 = ld_cvt4(gA);
    uint4 ra1 = ld_cvt4(gA + 64 * C_DIM);
    uint4 rb0 = ld_cvt4(gB);
    uint4 rb1 = ld_cvt4(gB + 64 * C_DIM);

    #pragma unroll 1
    for (int it = 0; it < 32; it++) {
        unsigned* bA = sA[it & 1];
        unsigned* bB = sB[it & 1];
        sts_perm(bA, lrow,      lc4, ra0);
        sts_perm(bA, lrow + 64, lc4, ra1);
        sts_perm(bB, lrow,      lc4, rb0);
        sts_perm(bB, lrow + 64, lc4, rb1);
        __syncthreads();

        if (it < 31) {
            const float* nA = gA + (it + 1) * 16;
            const float* nB = gB + (it + 1) * 16;
            ra0 = ld_cvt4(nA);
            ra1 = ld_cvt4(nA + 64 * C_DIM);
            rb0 = ld_cvt4(nB);
            rb1 = ld_cvt4(nB + 64 * C_DIM);
        }

        const unsigned* pa = bA + (wm + gid) * PITCH + (tig << 2);
        const unsigned* pb = bB + (wn + gid) * PITCH + (tig << 2);

        uint4 b4[4];
        #pragma unroll
        for (int ni = 0; ni < 4; ni++)
            b4[ni] = *(const uint4*)(pb + ni * 8 * PITCH);

        #pragma unroll
        for (int mi = 0; mi < 4; mi++) {
            uint4 alo = *(const uint4*)(pa + (mi * 16)     * PITCH);
            uint4 ahi = *(const uint4*)(pa + (mi * 16 + 8) * PITCH);
            #pragma unroll
            for (int ni = 0; ni < 4; ni++) {
                // kk = 0..7   (a0,a1,a2,a3) = (lo.x, hi.x, lo.y, hi.y)
                mma_tf32(acc[mi][ni], alo.x, ahi.x, alo.y, ahi.y, b4[ni].x, b4[ni].y);
                // kk = 8..15
                mma_tf32(acc[mi][ni], alo.z, ahi.z, alo.w, ahi.w, b4[ni].z, b4[ni].w);
            }
        }
    }

    // epilogue: c0=(gid,2tig) c1=(gid,2tig+1) c2=(gid+8,2tig) c3=(gid+8,2tig+1)
    const bool has_bias = (bias != nullptr);
    #pragma unroll
    for (int mi = 0; mi < 4; mi++) {
        #pragma unroll
        for (int ni = 0; ni < 4; ni++) {
            int r0 = m0 + wm + mi * 16 + gid;
            int cc = n0 + wn + ni * 8 + (tig << 1);
            float b0v = has_bias ? bias[cc]     : 0.f;
            float b1v = has_bias ? bias[cc + 1] : 0.f;
            float2 lo = make_float2(acc[mi][ni][0] * scale + b0v,
                                    acc[mi][ni][1] * scale + b1v);
            float2 hi = make_float2(acc[mi][ni][2] * scale + b0v,
                                    acc[mi][ni][3] * scale + b1v);
            *(float2*)&C[(size_t)r0       * C_DIM + cc] = lo;
            *(float2*)&C[(size_t)(r0 + 8) * C_DIM + cc] = hi;
        }
    }
}

// ============================================================================
// Kernel 2: per-pixel two-stage attention (unchanged from passing R8 kernel).
// ============================================================================
__global__ __launch_bounds__(64) void attn_kernel()
{
    __shared__ float qsp[8][68], ksp[8][68], vsp[8][68];
    __shared__ float nfq[8], nfk[8], nfv[8];
    __shared__ float A1raw[8][8];
    __shared__ float A1q[8][8], A1k[8][8];
    __shared__ float q2s[8][68], k2s[8][68];
    __shared__ float attnS[64][65];

    const int t = threadIdx.x;
    const int p = blockIdx.x;
    const float* gq = g_q + (size_t)p * C_DIM;
    const float* gk = g_k + (size_t)p * C_DIM;
    const float* gv = g_v + (size_t)p * C_DIM;

    #pragma unroll
    for (int i = 0; i < 8; i++) {
        qsp[i][t] = gq[i*64 + t];
        ksp[i][t] = gk[i*64 + t];
        vsp[i][t] = gv[i*64 + t];
    }
    __syncthreads();

    if (t < 24) {
        int m = t >> 3, h = t & 7;
        const float* src = (m == 0) ? &qsp[h][0] : (m == 1) ? &ksp[h][0] : &vsp[h][0];
        float ss = 0.f;
        #pragma unroll
        for (int d = 0; d < 64; d += 4) {
            float4 x4 = *(const float4*)&src[d];
            ss += x4.x*x4.x + x4.y*x4.y + x4.z*x4.z + x4.w*x4.w;
        }
        float nf = 1.0f / fmaxf(sqrtf(ss), 1e-12f);
        if (m == 0) nfq[h] = nf; else if (m == 1) nfk[h] = nf; else nfv[h] = nf;
    }
    __syncthreads();

    {
        int h = t >> 3, g = t & 7;
        float dot = 0.f;
        #pragma unroll
        for (int d = 0; d < 64; d += 4) {
            float4 a = *(const float4*)&vsp[h][d];
            float4 b = *(const float4*)&vsp[g][d];
            dot += a.x*b.x + a.y*b.y + a.z*b.z + a.w*b.w;
        }
        A1raw[h][g] = dot * nfv[h] * nfv[g];
    }
    __syncthreads();

    if (t < 8) {
        float r[8]; float mx = -1e30f;
        #pragma unroll
        for (int g = 0; g < 8; g++) { r[g] = A1raw[t][g]; mx = fmaxf(mx, r[g]); }
        float s = 0.f;
        #pragma unroll
        for (int g = 0; g < 8; g++) { r[g] = __expf(r[g] - mx); s += r[g]; }
        float inv = 1.0f / s;
        #pragma unroll
        for (int g = 0; g < 8; g++) {
            float pg = r[g] * inv;
            A1q[t][g] = pg * nfq[g];
            A1k[t][g] = pg * nfk[g];
        }
    }
    __syncthreads();

    {
        float aq[8] = {}, ak[8] = {};
        #pragma unroll
        for (int g = 0; g < 8; g++) {
            float qv = qsp[g][t], kv = ksp[g][t];
            #pragma unroll
            for (int h = 0; h < 8; h++) {
                aq[h] += A1q[h][g] * qv;
                ak[h] += A1k[h][g] * kv;
            }
        }
        #pragma unroll
        for (int h = 0; h < 8; h++) { q2s[h][t] = aq[h]; k2s[h][t] = ak[h]; }
    }
    __syncthreads();

    {
        float row[64];
        #pragma unroll
        for (int e = 0; e < 64; e++) row[e] = 0.f;
        #pragma unroll
        for (int h = 0; h < 8; h++) {
            float kh = k2s[h][t];
            #pragma unroll
            for (int e = 0; e < 64; e += 4) {
                float4 q4 = *(const float4*)&q2s[h][e];
                row[e+0] += kh * q4.x;
                row[e+1] += kh * q4.y;
                row[e+2] += kh * q4.z;
                row[e+3] += kh * q4.w;
            }
        }
        float mx = row[0];
        #pragma unroll
        for (int e = 1; e < 64; e++) mx = fmaxf(mx, row[e]);
        float s = 0.f;
        #pragma unroll
        for (int e = 0; e < 64; e++) { row[e] = __expf(row[e] - mx); s += row[e]; }
        float inv = 1.0f / s;
        #pragma unroll
        for (int e = 0; e < 64; e++) attnS[t][e] = row[e] * inv;
    }
    __syncthreads();

    float o[8] = {};
    #pragma unroll
    for (int d = 0; d < 64; d += 4) {
        float a0 = attnS[d+0][t], a1 = attnS[d+1][t];
        float a2 = attnS[d+2][t], a3 = attnS[d+3][t];
        #pragma unroll
        for (int h = 0; h < 8; h++) {
            float4 v4 = *(const float4*)&vsp[h][d];
            o[h] += v4.x*a0 + v4.y*a1 + v4.z*a2 + v4.w*a3;
        }
    }

    int bIdx = p >> 12;
    int nn   = p & 4095;
    int a    = nn >> 6, r = nn & 63;
    float* dstp = g_mid + (size_t)bIdx * 4096 * C_DIM
                        + ((size_t)t * 64 + a) * C_DIM + (r << 3);
    ((float4*)dstp)[0] = make_float4(o[0], o[1], o[2], o[3]);
    ((float4*)dstp)[1] = make_float4(o[4], o[5], o[6], o[7]);
}

// ============================================================================
extern "C" void kernel_launch(void* const* d_in, const int* in_sizes, int n_in,
                              void* d_out, int out_size)
{
    const float* x  = (const float*)d_in[0];
    const float* Wq = (const float*)d_in[1];
    const float* Wk = (const float*)d_in[2];
    const float* Wv = (const float*)d_in[3];
    // d_in[4] = conv_w : mathematically dead in the reference
    const float* Pw = (const float*)d_in[5];
    const float* Pb = (const float*)d_in[6];
    float* out = (float*)d_out;

    gemm_tf32_kernel<<<512, 256>>>(x, Wq, nullptr, nullptr, 0, 1.0f);
    gemm_tf32_kernel<<<512, 256>>>(x, Wk, nullptr, nullptr, 1, 1.0f);
    gemm_tf32_kernel<<<512, 256>>>(x, Wv, nullptr, nullptr, 2, 2.0f);
    attn_kernel<<<NPIX, 64>>>();
    gemm_tf32_kernel<<<512, 256>>>(nullptr, Pw, Pb, out, 3, 1.0f);
}

// round 16
// speedup vs baseline: 1.9109x; 1.0038x over previous
#include <cuda_runtime.h>
#include <math.h>

// Shapes fixed: b=4, h=w=64, c=512, HEADS=8, DIM_HEAD=64.
#define M_TOTAL 16384
#define C_DIM   512
#define NPIX    16384

// Scratch (no cudaMalloc allowed).
__device__ float g_q[M_TOTAL * C_DIM];
__device__ float g_k[M_TOTAL * C_DIM];
__device__ float g_v[M_TOTAL * C_DIM];   // 2 * (x @ Wv^T)
__device__ float g_mid[M_TOTAL * C_DIM]; // scrambled attention output

// ---- tf32 helpers ----
__device__ __forceinline__ unsigned f2tf32(float f) {
    unsigned r; asm("cvt.rna.tf32.f32 %0, %1;" : "=r"(r) : "f"(f)); return r;
}
__device__ __forceinline__ void mma_tf32(float c[4],
    unsigned a0, unsigned a1, unsigned a2, unsigned a3,
    unsigned b0, unsigned b1)
{
    asm("mma.sync.aligned.m16n8k8.row.col.f32.tf32.tf32.f32 "
        "{%0,%1,%2,%3},{%4,%5,%6,%7},{%8,%9},{%0,%1,%2,%3};"
        : "+f"(c[0]), "+f"(c[1]), "+f"(c[2]), "+f"(c[3])
        : "r"(a0), "r"(a1), "r"(a2), "r"(a3), "r"(b0), "r"(b1));
}

// ============================================================================
// Generic tf32 tensor-core GEMM:  C[m,n] = scale * sum_k A[m,k]*W[n,k] (+bias)
// M=16384, N=K=512. Block tile 128x128, 256 threads, warp tile 64x32.
// SMEM: pitch-20 rows (16 k-words + 4 pad) with k-interleave
//   k' = (k&3)*4 + (k>>2)   -> one LDS.128 per row serves both k8 substeps.
// Conflict-free: STS.128 fills, LDS.128 fragment reads (pitch-20 bank walk).
// Double-buffered, one __syncthreads per k16 iteration, register prefetch.
// dst: 0->g_q, 1->g_k, 2->g_v, 3-> A=g_mid, C=Cext (projection).
// ============================================================================
#define PITCH 20

__device__ __forceinline__ uint4 ld_cvt4(const float* p) {
    float4 v = *(const float4*)p;
    uint4 u; u.x = f2tf32(v.x); u.y = f2tf32(v.y); u.z = f2tf32(v.z); u.w = f2tf32(v.w);
    return u;
}
__device__ __forceinline__ void sts_perm(unsigned* buf, int row, int c4, uint4 u) {
    unsigned* p = buf + row * PITCH + c4;   // k' = j*4 + c4  (j = k&3)
    p[0] = u.x; p[4] = u.y; p[8] = u.z; p[12] = u.w;
}

__global__ __launch_bounds__(256, 2) void gemm_tf32_kernel(
    const float* __restrict__ A, const float* __restrict__ W,
    const float* __restrict__ bias, float* __restrict__ Cext,
    int dst, float scale)
{
    __shared__ unsigned sA[2][128 * PITCH];
    __shared__ unsigned sB[2][128 * PITCH];

    const float* Ap = (dst == 3) ? g_mid : A;
    float* C = (dst == 0) ? g_q : (dst == 1) ? g_k : (dst == 2) ? g_v : Cext;

    const int tid = threadIdx.x;
    const int bx  = blockIdx.x;
    const int m0  = (bx >> 2) << 7;          // 128 m-tiles
    const int n0  = (bx & 3)  << 7;          // 4 n-tiles

    // tile loaders: rows lrow and lrow+64, one float4 (k-chunk c4) each
    const int lrow = tid >> 2;
    const int lc4  = tid & 3;                // c' = k>>2
    const float* gA = Ap + (size_t)(m0 + lrow) * C_DIM + (lc4 << 2);
    const float* gB = W  + (size_t)(n0 + lrow) * C_DIM + (lc4 << 2);

    // warp coords
    const int w    = tid >> 5;
    const int lane = tid & 31;
    const int gid  = lane >> 2;
    const int tig  = lane & 3;
    const int wm   = (w >> 2) * 64;          // 0 / 64
    const int wn   = (w & 3)  * 32;          // 0 / 32 / 64 / 96

    float acc[4][4][4];
    #pragma unroll
    for (int i = 0; i < 4; i++)
        #pragma unroll
        for (int j = 0; j < 4; j++)
            #pragma unroll
            for (int q = 0; q < 4; q++) acc[i][j][q] = 0.f;

    uint4 ra0 = ld_cvt4(gA);
    uint4 ra1 = ld_cvt4(gA + 64 * C_DIM);
    uint4 rb0 = ld_cvt4(gB);
    uint4 rb1 = ld_cvt4(gB + 64 * C_DIM);

    #pragma unroll 1
    for (int it = 0; it < 32; it++) {
        unsigned* bA = sA[it & 1];
        unsigned* bB = sB[it & 1];
        sts_perm(bA, lrow,      lc4, ra0);
        sts_perm(bA, lrow + 64, lc4, ra1);
        sts_perm(bB, lrow,      lc4, rb0);
        sts_perm(bB, lrow + 64, lc4, rb1);
        __syncthreads();

        if (it < 31) {
            const float* nA = gA + (it + 1) * 16;
            const float* nB = gB + (it + 1) * 16;
            ra0 = ld_cvt4(nA);
            ra1 = ld_cvt4(nA + 64 * C_DIM);
            rb0 = ld_cvt4(nB);
            rb1 = ld_cvt4(nB + 64 * C_DIM);
        }

        const unsigned* pa = bA + (wm + gid) * PITCH + (tig << 2);
        const unsigned* pb = bB + (wn + gid) * PITCH + (tig << 2);

        uint4 b4[4];
        #pragma unroll
        for (int ni = 0; ni < 4; ni++)
            b4[ni] = *(const uint4*)(pb + ni * 8 * PITCH);

        #pragma unroll
        for (int mi = 0; mi < 4; mi++) {
            uint4 alo = *(const uint4*)(pa + (mi * 16)     * PITCH);
            uint4 ahi = *(const uint4*)(pa + (mi * 16 + 8) * PITCH);
            #pragma unroll
            for (int ni = 0; ni < 4; ni++) {
                // kk = 0..7   (a0,a1,a2,a3) = (lo.x, hi.x, lo.y, hi.y)
                mma_tf32(acc[mi][ni], alo.x, ahi.x, alo.y, ahi.y, b4[ni].x, b4[ni].y);
                // kk = 8..15
                mma_tf32(acc[mi][ni], alo.z, ahi.z, alo.w, ahi.w, b4[ni].z, b4[ni].w);
            }
        }
    }

    // epilogue: c0=(gid,2tig) c1=(gid,2tig+1) c2=(gid+8,2tig) c3=(gid+8,2tig+1)
    const bool has_bias = (bias != nullptr);
    #pragma unroll
    for (int mi = 0; mi < 4; mi++) {
        #pragma unroll
        for (int ni = 0; ni < 4; ni++) {
            int r0 = m0 + wm + mi * 16 + gid;
            int cc = n0 + wn + ni * 8 + (tig << 1);
            float b0v = has_bias ? bias[cc]     : 0.f;
            float b1v = has_bias ? bias[cc + 1] : 0.f;
            float2 lo = make_float2(acc[mi][ni][0] * scale + b0v,
                                    acc[mi][ni][1] * scale + b1v);
            float2 hi = make_float2(acc[mi][ni][2] * scale + b0v,
                                    acc[mi][ni][3] * scale + b1v);
            *(float2*)&C[(size_t)r0       * C_DIM + cc] = lo;
            *(float2*)&C[(size_t)(r0 + 8) * C_DIM + cc] = hi;
        }
    }
}

// ============================================================================
// Kernel 2: per-pixel two-stage attention (unchanged from passing R8 kernel).
// ============================================================================
__global__ __launch_bounds__(64) void attn_kernel()
{
    __shared__ float qsp[8][68], ksp[8][68], vsp[8][68];
    __shared__ float nfq[8], nfk[8], nfv[8];
    __shared__ float A1raw[8][8];
    __shared__ float A1q[8][8], A1k[8][8];
    __shared__ float q2s[8][68], k2s[8][68];
    __shared__ float attnS[64][65];

    const int t = threadIdx.x;
    const int p = blockIdx.x;
    const float* gq = g_q + (size_t)p * C_DIM;
    const float* gk = g_k + (size_t)p * C_DIM;
    const float* gv = g_v + (size_t)p * C_DIM;

    #pragma unroll
    for (int i = 0; i < 8; i++) {
        qsp[i][t] = gq[i*64 + t];
        ksp[i][t] = gk[i*64 + t];
        vsp[i][t] = gv[i*64 + t];
    }
    __syncthreads();

    if (t < 24) {
        int m = t >> 3, h = t & 7;
        const float* src = (m == 0) ? &qsp[h][0] : (m == 1) ? &ksp[h][0] : &vsp[h][0];
        float ss = 0.f;
        #pragma unroll
        for (int d = 0; d < 64; d += 4) {
            float4 x4 = *(const float4*)&src[d];
            ss += x4.x*x4.x + x4.y*x4.y + x4.z*x4.z + x4.w*x4.w;
        }
        float nf = 1.0f / fmaxf(sqrtf(ss), 1e-12f);
        if (m == 0) nfq[h] = nf; else if (m == 1) nfk[h] = nf; else nfv[h] = nf;
    }
    __syncthreads();

    {
        int h = t >> 3, g = t & 7;
        float dot = 0.f;
        #pragma unroll
        for (int d = 0; d < 64; d += 4) {
            float4 a = *(const float4*)&vsp[h][d];
            float4 b = *(const float4*)&vsp[g][d];
            dot += a.x*b.x + a.y*b.y + a.z*b.z + a.w*b.w;
        }
        A1raw[h][g] = dot * nfv[h] * nfv[g];
    }
    __syncthreads();

    if (t < 8) {
        float r[8]; float mx = -1e30f;
        #pragma unroll
        for (int g = 0; g < 8; g++) { r[g] = A1raw[t][g]; mx = fmaxf(mx, r[g]); }
        float s = 0.f;
        #pragma unroll
        for (int g = 0; g < 8; g++) { r[g] = __expf(r[g] - mx); s += r[g]; }
        float inv = 1.0f / s;
        #pragma unroll
        for (int g = 0; g < 8; g++) {
            float pg = r[g] * inv;
            A1q[t][g] = pg * nfq[g];
            A1k[t][g] = pg * nfk[g];
        }
    }
    __syncthreads();

    {
        float aq[8] = {}, ak[8] = {};
        #pragma unroll
        for (int g = 0; g < 8; g++) {
            float qv = qsp[g][t], kv = ksp[g][t];
            #pragma unroll
            for (int h = 0; h < 8; h++) {
                aq[h] += A1q[h][g] * qv;
                ak[h] += A1k[h][g] * kv;
            }
        }
        #pragma unroll
        for (int h = 0; h < 8; h++) { q2s[h][t] = aq[h]; k2s[h][t] = ak[h]; }
    }
    __syncthreads();

    {
        float row[64];
        #pragma unroll
        for (int e = 0; e < 64; e++) row[e] = 0.f;
        #pragma unroll
        for (int h = 0; h < 8; h++) {
            float kh = k2s[h][t];
            #pragma unroll
            for (int e = 0; e < 64; e += 4) {
                float4 q4 = *(const float4*)&q2s[h][e];
                row[e+0] += kh * q4.x;
                row[e+1] += kh * q4.y;
                row[e+2] += kh * q4.z;
                row[e+3] += kh * q4.w;
            }
        }
        float mx = row[0];
        #pragma unroll
        for (int e = 1; e < 64; e++) mx = fmaxf(mx, row[e]);
        float s = 0.f;
        #pragma unroll
        for (int e = 0; e < 64; e++) { row[e] = __expf(row[e] - mx); s += row[e]; }
        float inv = 1.0f / s;
        #pragma unroll
        for (int e = 0; e < 64; e++) attnS[t][e] = row[e] * inv;
    }
    __syncthreads();

    float o[8] = {};
    #pragma unroll
    for (int d = 0; d < 64; d += 4) {
        float a0 = attnS[d+0][t], a1 = attnS[d+1][t];
        float a2 = attnS[d+2][t], a3 = attnS[d+3][t];
        #pragma unroll
        for (int h = 0; h < 8; h++) {
            float4 v4 = *(const float4*)&vsp[h][d];
            o[h] += v4.x*a0 + v4.y*a1 + v4.z*a2 + v4.w*a3;
        }
    }

    int bIdx = p >> 12;
    int nn   = p & 4095;
    int a    = nn >> 6, r = nn & 63;
    float* dstp = g_mid + (size_t)bIdx * 4096 * C_DIM
                        + ((size_t)t * 64 + a) * C_DIM + (r << 3);
    ((float4*)dstp)[0] = make_float4(o[0], o[1], o[2], o[3]);
    ((float4*)dstp)[1] = make_float4(o[4], o[5], o[6], o[7]);
}

// ============================================================================
extern "C" void kernel_launch(void* const* d_in, const int* in_sizes, int n_in,
                              void* d_out, int out_size)
{
    const float* x  = (const float*)d_in[0];
    const float* Wq = (const float*)d_in[1];
    const float* Wk = (const float*)d_in[2];
    const float* Wv = (const float*)d_in[3];
    // d_in[4] = conv_w : mathematically dead in the reference
    const float* Pw = (const float*)d_in[5];
    const float* Pb = (const float*)d_in[6];
    float* out = (float*)d_out;

    gemm_tf32_kernel<<<512, 256>>>(x, Wq, nullptr, nullptr, 0, 1.0f);
    gemm_tf32_kernel<<<512, 256>>>(x, Wk, nullptr, nullptr, 1, 1.0f);
    gemm_tf32_kernel<<<512, 256>>>(x, Wv, nullptr, nullptr, 2, 2.0f);
    attn_kernel<<<NPIX, 64>>>();
    gemm_tf32_kernel<<<512, 256>>>(nullptr, Pw, Pb, out, 3, 1.0f);
}